// round 16
// baseline (speedup 1.0000x reference)
#include <cuda_runtime.h>
#include <cuda_fp16.h>
#include <stdint.h>

// ---------------- problem constants -----------------------------------------
#define LL 4096
#define BB 4
#define DD 1024
#define HH 16
#define HD 64
#define ROWS (LL*BB)          // 16384
#define BH   (BB*HH)          // 64
#define KV_PARTS 8
#define LPART (LL/KV_PARTS)   // 512

// ---------------- scratch (device globals; cudaMalloc is banned) ------------
__device__ __align__(256) __half g_xh  [(size_t)ROWS*DD];    // X in f16
__device__ __align__(256) __half g_wh  [(size_t)3*DD*DD];    // [Wq;Wk;Wv] f16
__device__ __align__(256) __half g_woph[(size_t)DD*DD];      // Wo permuted f16
__device__ __align__(256) float  g_bqkv[(size_t)3*DD];       // [bq;bk;bv]
__device__ __align__(256) __half g_qh  [(size_t)ROWS*DD];    // q (unscaled) f16
__device__ __align__(256) __half g_kh  [(size_t)ROWS*DD];
__device__ __align__(256) __half g_vh  [(size_t)ROWS*DD];
__device__ __align__(256) __half g_ah  [(size_t)ROWS*DD];    // attn out f16
__device__ __align__(256) float  g_kvp [(size_t)KV_PARTS*BH*HD*HD];  // f32 partials
__device__ __align__(256) __half g_kvTh[(size_t)BH*HD*HD];   // reduced KV^T, f16

// ---------------- helpers -----------------------------------------------------
__device__ __forceinline__ uint32_t smem_u32(const void* p) {
    uint32_t a;
    asm("{ .reg .u64 t; cvta.to.shared.u64 t, %1; cvt.u32.u64 %0, t; }" : "=r"(a) : "l"(p));
    return a;
}
__device__ __forceinline__ void cp16(uint32_t saddr, const void* gaddr) {
    asm volatile("cp.async.cg.shared.global [%0], [%1], 16;" :: "r"(saddr), "l"(gaddr));
}
__device__ __forceinline__ void ldsm4(uint32_t* r, uint32_t a) {
    asm volatile("ldmatrix.sync.aligned.m8n8.x4.shared.b16 {%0,%1,%2,%3}, [%4];"
        : "=r"(r[0]), "=r"(r[1]), "=r"(r[2]), "=r"(r[3]) : "r"(a));
}
__device__ __forceinline__ void ldsm4t(uint32_t* r, uint32_t a) {
    asm volatile("ldmatrix.sync.aligned.m8n8.x4.trans.shared.b16 {%0,%1,%2,%3}, [%4];"
        : "=r"(r[0]), "=r"(r[1]), "=r"(r[2]), "=r"(r[3]) : "r"(a));
}
__device__ __forceinline__ void mma16(float c[4], const uint32_t a[4],
                                      uint32_t b0, uint32_t b1) {
    asm volatile(
        "mma.sync.aligned.m16n8k16.row.col.f32.f16.f16.f32 "
        "{%0,%1,%2,%3}, {%4,%5,%6,%7}, {%8,%9}, {%0,%1,%2,%3};"
        : "+f"(c[0]), "+f"(c[1]), "+f"(c[2]), "+f"(c[3])
        : "r"(a[0]), "r"(a[1]), "r"(a[2]), "r"(a[3]), "r"(b0), "r"(b1));
}

// =============================================================================
// prep_all: block-range dispatch (Wo permute moved to side stream)
//   [0, 16384)            x -> f16
//   [16384, 19456)        pack Wq/Wk/Wv -> f16
//   [19456, 19468)        pack biases
// =============================================================================
__global__ void prep_all(const float* __restrict__ X,
                         const float* __restrict__ Wq, const float* __restrict__ Wk,
                         const float* __restrict__ Wv,
                         const float* __restrict__ bq, const float* __restrict__ bk,
                         const float* __restrict__ bv) {
    const int blk = blockIdx.x;
    const int tid = threadIdx.x;
    if (blk < 16384) {
        size_t i = ((size_t)blk * 256 + tid) * 4;
        float4 v = *(const float4*)(X + i);
        *(__half2*)(g_xh + i)     = __floats2half2_rn(v.x, v.y);
        *(__half2*)(g_xh + i + 2) = __floats2half2_rn(v.z, v.w);
    } else if (blk < 19456) {
        int r = blk - 16384;                            // 0..3071
        const float* src = (r < 1024) ? Wq : (r < 2048) ? Wk : Wv;
        int lr = r & 1023;
        int c = tid * 4;
        float4 v = *(const float4*)(src + (size_t)lr * DD + c);
        *(__half2*)(g_wh + (size_t)r * DD + c)     = __floats2half2_rn(v.x, v.y);
        *(__half2*)(g_wh + (size_t)r * DD + c + 2) = __floats2half2_rn(v.z, v.w);
    } else {
        int idx = (blk - 19456) * 256 + tid;            // 0..3071
        int t = idx >> 10;
        const float* src = (t == 0) ? bq : (t == 1) ? bk : bv;
        g_bqkv[idx] = src[idx & 1023];
    }
}

// g_woph[j][h*64+t] = half(Wo[j][t*16+h])   (side stream; overlaps kv-GEMM)
__global__ void wo_permute_h(const float* __restrict__ Wo) {
    __shared__ float srow[DD];
    const int j = blockIdx.x, tid = threadIdx.x;
#pragma unroll
    for (int i = 0; i < 4; ++i) srow[tid + 256*i] = Wo[(size_t)j*DD + tid + 256*i];
    __syncthreads();
#pragma unroll
    for (int i = 0; i < 4; ++i) {
        int f = tid + 256*i;                             // f = h*64 + t
        g_woph[(size_t)j*DD + f] = __float2half_rn(srow[((f & 63) << 4) | (f >> 6)]);
    }
}

// =============================================================================
// FP16 tensor-core GEMM:  C = A @ B^T + bias   (frozen at R11)
// =============================================================================
#define STA  16384                 // A stage bytes (128 rows x 128B)
#define STS_ (2*STA)               // 32768
#define GSMEM (3 * STS_)           // 98304
#define NKT  16                    // 1024 / 64

__global__ void __launch_bounds__(128, 2) gemm_h(
    const __half* __restrict__ A, const __half* __restrict__ B,
    const float* __restrict__ bias,
    void* __restrict__ o0, void* __restrict__ o1, void* __restrict__ o2,
    int half_out)
{
    extern __shared__ char smem[];
    const uint32_t sb = smem_u32(smem);
    const int tid  = threadIdx.x;
    const int wid  = tid >> 5;
    const int lane = tid & 31;
    const int n0 = blockIdx.x * 128;
    const int m0 = blockIdx.y * 128;
    const int wm = (wid & 1) * 64;
    const int wn = (wid >> 1) * 64;

    const int row0 = tid >> 3, seg = tid & 7;
    const uint32_t sm_base = (uint32_t)(row0*128 + ((seg ^ (row0 & 7)) << 4));
    const char* Abase = (const char*)A + (size_t)m0 * 2048 + row0*2048 + seg*16;
    const char* Bbase = (const char*)B + (size_t)n0 * 2048 + row0*2048 + seg*16;

#define LOADC(c) do {                                                    \
        uint32_t ab_ = sb + ((c) % 3)*STS_ + sm_base;                    \
        uint32_t bb_ = ab_ + STA;                                        \
        const char* ga_ = Abase + (size_t)(c)*128;                       \
        const char* gb_ = Bbase + (size_t)(c)*128;                       \
        _Pragma("unroll") for (int i_ = 0; i_ < 8; ++i_) {               \
            cp16(ab_ + i_*2048, ga_ + i_*32768);                         \
            cp16(bb_ + i_*2048, gb_ + i_*32768);                         \
        }                                                                \
        asm volatile("cp.async.commit_group;" ::: "memory");             \
    } while (0)

    const int a_row = wm + (lane & 15);
    const int b_row = wn + (lane & 7) + ((lane >> 4) << 3);
    const int lo4   = (lane & 7) << 4;
    const int a_hi  = lane >> 4;
    const int b_hi  = (lane >> 3) & 1;

    float acc[4][8][4];
#pragma unroll
    for (int i = 0; i < 4; ++i)
#pragma unroll
        for (int j = 0; j < 8; ++j)
#pragma unroll
            for (int t = 0; t < 4; ++t) acc[i][j][t] = 0.f;

    LOADC(0);
    LOADC(1);

    for (int kt = 0; kt < NKT; ++kt) {
        if (kt + 1 < NKT) asm volatile("cp.async.wait_group 1;" ::: "memory");
        else              asm volatile("cp.async.wait_group 0;" ::: "memory");
        __syncthreads();

        const bool do_load = (kt + 2 < NKT);
        const uint32_t nab = sb + ((kt + 2) % 3)*STS_ + sm_base;
        const uint32_t nbb = nab + STA;
        const char* nga = Abase + (size_t)(kt + 2)*128;
        const char* ngb = Bbase + (size_t)(kt + 2)*128;

        const uint32_t sa = sb + (kt % 3) * STS_;
        const uint32_t aB = sa + a_row*128;
        const uint32_t bB = sa + STA + b_row*128;

#pragma unroll
        for (int s = 0; s < 4; ++s) {
            uint32_t af[4][4], bf[4][4];
            const uint32_t asg = (uint32_t)(((2*s + a_hi) << 4) ^ lo4);
            const uint32_t bsg = (uint32_t)(((2*s + b_hi) << 4) ^ lo4);
#pragma unroll
            for (int mt = 0; mt < 4; ++mt)
                ldsm4(af[mt], aB + mt*2048 + asg);
#pragma unroll
            for (int p = 0; p < 4; ++p)
                ldsm4(bf[p], bB + p*2048 + bsg);
            if (do_load) {
                cp16(nab + (2*s  )*2048, nga + (size_t)(2*s  )*32768);
                cp16(nab + (2*s+1)*2048, nga + (size_t)(2*s+1)*32768);
                cp16(nbb + (2*s  )*2048, ngb + (size_t)(2*s  )*32768);
                cp16(nbb + (2*s+1)*2048, ngb + (size_t)(2*s+1)*32768);
            }
#pragma unroll
            for (int mt = 0; mt < 4; ++mt)
#pragma unroll
                for (int nt = 0; nt < 8; ++nt)
                    mma16(acc[mt][nt], af[mt],
                          bf[nt >> 1][(nt & 1) * 2], bf[nt >> 1][(nt & 1) * 2 + 1]);
        }
        if (do_load)
            asm volatile("cp.async.commit_group;" ::: "memory");
    }

    if (half_out) {
        const int t = n0 >> 10;
        __half* outp = (t == 0) ? (__half*)o0 : (t == 1) ? (__half*)o1 : (__half*)o2;
#pragma unroll
        for (int mt = 0; mt < 4; ++mt) {
#pragma unroll
            for (int nt = 0; nt < 8; ++nt) {
                int row = m0 + wm + mt*16 + (lane >> 2);
                int gn  = n0 + wn + nt*8 + 2*(lane & 3);
                int col = gn & 1023;
                float b0 = bias[gn], b1 = bias[gn + 1];
                *(__half2*)&outp[(size_t)row * 1024 + col] =
                    __floats2half2_rn(acc[mt][nt][0] + b0, acc[mt][nt][1] + b1);
                *(__half2*)&outp[(size_t)(row + 8) * 1024 + col] =
                    __floats2half2_rn(acc[mt][nt][2] + b0, acc[mt][nt][3] + b1);
            }
        }
    } else {
        float* outp = (float*)o0;
#pragma unroll
        for (int mt = 0; mt < 4; ++mt) {
#pragma unroll
            for (int nt = 0; nt < 8; ++nt) {
                int row = m0 + wm + mt*16 + (lane >> 2);
                int gn  = n0 + wn + nt*8 + 2*(lane & 3);
                float b0 = bias[gn], b1 = bias[gn + 1];
                *(float2*)&outp[(size_t)row * 1024 + gn] =
                    make_float2(acc[mt][nt][0] + b0, acc[mt][nt][1] + b1);
                *(float2*)&outp[(size_t)(row + 8) * 1024 + gn] =
                    make_float2(acc[mt][nt][2] + b0, acc[mt][nt][3] + b1);
            }
        }
    }
}

// =============================================================================
// partial KV^T per (b,h): kvT[e][d] = sum_l v[l][e]*k[l][d]
// f16 mma16 with ldmatrix.trans; cp.async staging; f32 partial output (R14).
// =============================================================================
#define KVCH (LPART/32)            // 16 chunks of 32 l-rows

__global__ void __launch_bounds__(256) kv_partial()
{
    const int bh = blockIdx.x, part = blockIdx.y;
    const int b = bh >> 4, h = bh & 15;

    __shared__ __half vs[3][32*64];
    __shared__ __half ks[3][32*64];
    const uint32_t vsb = smem_u32(vs);
    const uint32_t ksb = smem_u32(ks);

    const int tid  = threadIdx.x;
    const int lane = tid & 31;
    const int warp = tid >> 5;
    const int e0 = (warp >> 1) * 16;
    const int d0 = (warp & 1) * 32;

    const int srow = tid >> 3, sseg = tid & 7;
    const uint32_t sm_off = (uint32_t)(srow*128 + ((sseg ^ (srow & 7)) << 4));
    const size_t gbase = ((size_t)(part * LPART + srow) * BB + b) * DD
                       + (size_t)h * 64 + sseg * 8;

#define LOADKV(c) do {                                                   \
        size_t g_ = gbase + (size_t)(c) * 32 * BB * DD;                  \
        cp16(vsb + ((c) % 3) * 4096 + sm_off, g_vh + g_);                \
        cp16(ksb + ((c) % 3) * 4096 + sm_off, g_kh + g_);                \
        asm volatile("cp.async.commit_group;" ::: "memory");             \
    } while (0)

    const int a_lrow = (lane & 7) + ((lane >> 4) << 3);
    const int b_lrow = (lane & 7) + (((lane >> 3) & 1) << 3);
    const int a_cbyte = e0*2 + (((lane >> 3) & 1) << 4);
    const int b_cbyte0 = d0*2 + (((lane >> 4) & 1) << 4);

    float acc[4][4];
#pragma unroll
    for (int i = 0; i < 4; ++i)
#pragma unroll
        for (int t = 0; t < 4; ++t) acc[i][t] = 0.f;

    LOADKV(0);
    LOADKV(1);

    for (int it = 0; it < KVCH; ++it) {
        if (it + 1 < KVCH) asm volatile("cp.async.wait_group 1;" ::: "memory");
        else               asm volatile("cp.async.wait_group 0;" ::: "memory");
        __syncthreads();
        if (it + 2 < KVCH) LOADKV(it + 2);

        const uint32_t vB = vsb + (it % 3) * 4096;
        const uint32_t kB = ksb + (it % 3) * 4096;

#pragma unroll
        for (int s = 0; s < 2; ++s) {
            uint32_t af[4], bf[2][4];
            {
                int r = 16*s + a_lrow;
                ldsm4t(af, vB + r*128 + (uint32_t)(((a_cbyte >> 4) ^ (r & 7)) << 4));
            }
#pragma unroll
            for (int p = 0; p < 2; ++p) {
                int r = 16*s + b_lrow;
                int cb = b_cbyte0 + p*32;
                ldsm4t(bf[p], kB + r*128 + (uint32_t)(((cb >> 4) ^ (r & 7)) << 4));
            }
#pragma unroll
            for (int nt = 0; nt < 4; ++nt)
                mma16(acc[nt], af,
                      bf[nt >> 1][(nt & 1) * 2], bf[nt >> 1][(nt & 1) * 2 + 1]);
        }
        __syncthreads();
    }

    float* out = g_kvp + ((size_t)part * BH + bh) * 4096;
#pragma unroll
    for (int nt = 0; nt < 4; ++nt) {
        int e = e0 + (lane >> 2);
        int d = d0 + nt*8 + 2*(lane & 3);
        *(float2*)&out[(e    ) * 64 + d] = make_float2(acc[nt][0], acc[nt][1]);
        *(float2*)&out[(e + 8) * 64 + d] = make_float2(acc[nt][2], acc[nt][3]);
    }
}

// deterministic fixed-order reduce; grid (BH, 16); output f16
__global__ void kv_reduce() {
    const int bh = blockIdx.x;
    const int i  = blockIdx.y * 256 + threadIdx.x;      // 0..4095
    float s = 0.f;
#pragma unroll
    for (int p = 0; p < KV_PARTS; ++p)
        s += g_kvp[((size_t)p * BH + bh) * 4096 + i];
    g_kvTh[(size_t)bh * 4096 + i] = __float2half_rn(s);
}

// =============================================================================
// attn = (q @ kvT^T) * (0.125/scalar) per (b,h)   (frozen at R12)
// =============================================================================
__global__ void __launch_bounds__(128) attn_qkv(const float* __restrict__ scalar_ptr)
{
    const int lc = blockIdx.x;
    const int h  = blockIdx.y;
    const int b  = blockIdx.z;
    const int bh = b * 16 + h;
    const int l0 = lc * 64;

    __shared__ __half qs [64 * 64];
    __shared__ __half kvs[64 * 64];

    const uint32_t qsb = smem_u32(qs);
    const uint32_t kvb = smem_u32(kvs);

    const int tid  = threadIdx.x;
    const int lane = tid & 31;
    const int warp = tid >> 5;
    const int wm   = warp * 16;

#pragma unroll
    for (int i = 0; i < 4; ++i) {
        int s   = tid + 128 * i;
        int row = s >> 3, seg = s & 7;
        uint32_t dst = (uint32_t)(row*128 + ((seg ^ (row & 7)) << 4));
        const __half* qg = g_qh + ((size_t)(l0 + row) * BB + b) * DD
                                + (size_t)h * 64 + seg * 8;
        const __half* kg = g_kvTh + (size_t)bh * 4096 + (size_t)s * 8;
        cp16(qsb + dst, qg);
        cp16(kvb + dst, kg);
    }
    asm volatile("cp.async.commit_group;" ::: "memory");
    asm volatile("cp.async.wait_group 0;" ::: "memory");
    __syncthreads();

    const int a_row = wm + (lane & 15);
    const int b_row = (lane & 7) + ((lane >> 4) << 3);
    const int lo4   = (lane & 7) << 4;
    const int a_hi  = lane >> 4;
    const int b_hi  = (lane >> 3) & 1;
    const uint32_t aB = qsb + a_row*128;
    const uint32_t bB = kvb + b_row*128;

    float acc[8][4];
#pragma unroll
    for (int i = 0; i < 8; ++i)
#pragma unroll
        for (int t = 0; t < 4; ++t) acc[i][t] = 0.f;

#pragma unroll
    for (int s = 0; s < 4; ++s) {
        uint32_t af[4], bf[4][4];
        const uint32_t asg = (uint32_t)(((2*s + a_hi) << 4) ^ lo4);
        const uint32_t bsg = (uint32_t)(((2*s + b_hi) << 4) ^ lo4);
        ldsm4(af, aB + asg);
#pragma unroll
        for (int p = 0; p < 4; ++p)
            ldsm4(bf[p], bB + p*2048 + bsg);
#pragma unroll
        for (int nt = 0; nt < 8; ++nt)
            mma16(acc[nt], af,
                  bf[nt >> 1][(nt & 1) * 2], bf[nt >> 1][(nt & 1) * 2 + 1]);
    }

    const float scale = 0.125f / (*scalar_ptr);
#pragma unroll
    for (int nt = 0; nt < 8; ++nt) {
        int l = l0 + wm + (lane >> 2);
        int e = nt*8 + 2*(lane & 3);
        size_t o0 = ((size_t)l * BB + b) * DD + (size_t)h * 64 + e;
        size_t o1 = ((size_t)(l + 8) * BB + b) * DD + (size_t)h * 64 + e;
        *(__half2*)&g_ah[o0] = __floats2half2_rn(acc[nt][0]*scale, acc[nt][1]*scale);
        *(__half2*)&g_ah[o1] = __floats2half2_rn(acc[nt][2]*scale, acc[nt][3]*scale);
    }
}

// =============================================================================
// launch: prep_all (no Wo); wo_permute on side stream; kv-proj;
// fork q-proj || kv chain; join; attn; out-proj.
// =============================================================================
extern "C" void kernel_launch(void* const* d_in, const int* in_sizes, int n_in,
                              void* d_out, int out_size) {
    const float* x      = (const float*)d_in[0];
    const float* Wq     = (const float*)d_in[2];
    const float* bq     = (const float*)d_in[3];
    const float* Wk     = (const float*)d_in[4];
    const float* bk     = (const float*)d_in[5];
    const float* Wv     = (const float*)d_in[6];
    const float* bv     = (const float*)d_in[7];
    const float* Wo     = (const float*)d_in[8];
    const float* bo     = (const float*)d_in[9];
    const float* scalar = (const float*)d_in[10];
    float* out = (float*)d_out;

    __half *xh, *wh, *woph, *ah, *qh, *kh, *vh;
    float *bqkv;
    cudaGetSymbolAddress((void**)&xh,   g_xh);
    cudaGetSymbolAddress((void**)&wh,   g_wh);
    cudaGetSymbolAddress((void**)&woph, g_woph);
    cudaGetSymbolAddress((void**)&ah,   g_ah);
    cudaGetSymbolAddress((void**)&qh,   g_qh);
    cudaGetSymbolAddress((void**)&kh,   g_kh);
    cudaGetSymbolAddress((void**)&vh,   g_vh);
    cudaGetSymbolAddress((void**)&bqkv, g_bqkv);

    static cudaStream_t s2 = nullptr;
    static cudaEvent_t ev0 = nullptr, ev1 = nullptr, ev2 = nullptr;
    if (!s2) {
        cudaStreamCreateWithFlags(&s2, cudaStreamNonBlocking);
        cudaEventCreateWithFlags(&ev0, cudaEventDisableTiming);
        cudaEventCreateWithFlags(&ev1, cudaEventDisableTiming);
        cudaEventCreateWithFlags(&ev2, cudaEventDisableTiming);
        cudaFuncSetAttribute(gemm_h, cudaFuncAttributeMaxDynamicSharedMemorySize,
                             GSMEM);
    }

    // fork side stream; Wo permute runs concurrent with prep/kv-GEMM
    cudaEventRecord(ev0, 0);
    cudaStreamWaitEvent(s2, ev0, 0);
    wo_permute_h<<<DD, 256, 0, s2>>>(Wo);

    // serial prep on main: x->f16, pack W, pack biases
    prep_all<<<19468, 256>>>(x, Wq, Wk, Wv, bq, bk, bv);

    // k,v projection: N = 2048 (weights rows [1024, 3072) of g_wh)
    gemm_h<<<dim3(2*DD/128, ROWS/128), 128, GSMEM>>>(
        xh, wh + (size_t)DD*DD, bqkv + DD, kh, vh, vh, 1);

    // fork: kv chain on side stream, q projection on main stream (concurrent)
    cudaEventRecord(ev1, 0);
    cudaStreamWaitEvent(s2, ev1, 0);
    kv_partial<<<dim3(BH, KV_PARTS), 256, 0, s2>>>();
    kv_reduce<<<dim3(BH, 16), 256, 0, s2>>>();
    cudaEventRecord(ev2, s2);

    // q projection: N = 1024
    gemm_h<<<dim3(DD/128, ROWS/128), 128, GSMEM>>>(
        xh, wh, bqkv, qh, qh, qh, 1);

    // join (also orders wo_permute before out-proj, transitively via s2 order)
    cudaStreamWaitEvent(0, ev2, 0);

    attn_qkv<<<dim3(LL / 64, HH, BB), 128>>>(scalar);

    // output projection: N = 1024, fp32 output
    gemm_h<<<dim3(DD/128, ROWS/128), 128, GSMEM>>>(
        ah, woph, bo, out, out, out, 0);
}

// round 17
// speedup vs baseline: 1.0214x; 1.0214x over previous
#include <cuda_runtime.h>
#include <cuda_fp16.h>
#include <stdint.h>

// ---------------- problem constants -----------------------------------------
#define LL 4096
#define BB 4
#define DD 1024
#define HH 16
#define HD 64
#define ROWS (LL*BB)          // 16384
#define BH   (BB*HH)          // 64
#define KV_PARTS 8
#define LPART (LL/KV_PARTS)   // 512

// ---------------- scratch (device globals; cudaMalloc is banned) ------------
__device__ __align__(256) __half g_xh  [(size_t)ROWS*DD];    // X in f16
__device__ __align__(256) __half g_wh  [(size_t)3*DD*DD];    // [Wq;Wk;Wv] f16
__device__ __align__(256) __half g_woph[(size_t)DD*DD];      // Wo permuted f16
__device__ __align__(256) float  g_bqkv[(size_t)3*DD];       // [bq;bk;bv]
__device__ __align__(256) __half g_qh  [(size_t)ROWS*DD];    // q (unscaled) f16
__device__ __align__(256) __half g_kh  [(size_t)ROWS*DD];
__device__ __align__(256) __half g_vh  [(size_t)ROWS*DD];
__device__ __align__(256) __half g_ah  [(size_t)ROWS*DD];    // attn out f16
__device__ __align__(256) float  g_kvp [(size_t)KV_PARTS*BH*HD*HD];  // f32 partials
__device__ __align__(256) __half g_kvTh[(size_t)BH*HD*HD];   // reduced KV^T, f16

// ---------------- helpers -----------------------------------------------------
__device__ __forceinline__ uint32_t smem_u32(const void* p) {
    uint32_t a;
    asm("{ .reg .u64 t; cvta.to.shared.u64 t, %1; cvt.u32.u64 %0, t; }" : "=r"(a) : "l"(p));
    return a;
}
__device__ __forceinline__ void cp16(uint32_t saddr, const void* gaddr) {
    asm volatile("cp.async.cg.shared.global [%0], [%1], 16;" :: "r"(saddr), "l"(gaddr));
}
__device__ __forceinline__ void ldsm4(uint32_t* r, uint32_t a) {
    asm volatile("ldmatrix.sync.aligned.m8n8.x4.shared.b16 {%0,%1,%2,%3}, [%4];"
        : "=r"(r[0]), "=r"(r[1]), "=r"(r[2]), "=r"(r[3]) : "r"(a));
}
__device__ __forceinline__ void ldsm4t(uint32_t* r, uint32_t a) {
    asm volatile("ldmatrix.sync.aligned.m8n8.x4.trans.shared.b16 {%0,%1,%2,%3}, [%4];"
        : "=r"(r[0]), "=r"(r[1]), "=r"(r[2]), "=r"(r[3]) : "r"(a));
}
__device__ __forceinline__ void mma16(float c[4], const uint32_t a[4],
                                      uint32_t b0, uint32_t b1) {
    asm volatile(
        "mma.sync.aligned.m16n8k16.row.col.f32.f16.f16.f32 "
        "{%0,%1,%2,%3}, {%4,%5,%6,%7}, {%8,%9}, {%0,%1,%2,%3};"
        : "+f"(c[0]), "+f"(c[1]), "+f"(c[2]), "+f"(c[3])
        : "r"(a[0]), "r"(a[1]), "r"(a[2]), "r"(a[3]), "r"(b0), "r"(b1));
}

// =============================================================================
// prep_all: single serial kernel (R14 structure) with 4x ILP on X conversion.
//   [0, 4096)      x -> f16, 4 strided float4 chunks per thread (MLP=4)
//   [4096, 7168)   pack Wq/Wk/Wv -> f16
//   [7168, 8192)   Wo permute -> f16
//   [8192, 8204)   biases
// =============================================================================
#define XCHUNK ((size_t)4096 * 256 * 4)   // elements per strided chunk

__global__ void prep_all(const float* __restrict__ X,
                         const float* __restrict__ Wq, const float* __restrict__ Wk,
                         const float* __restrict__ Wv,
                         const float* __restrict__ bq, const float* __restrict__ bk,
                         const float* __restrict__ bv,
                         const float* __restrict__ Wo) {
    const int blk = blockIdx.x;
    const int tid = threadIdx.x;
    if (blk < 4096) {
        size_t i = ((size_t)blk * 256 + tid) * 4;
        float4 v0 = *(const float4*)(X + i);
        float4 v1 = *(const float4*)(X + i + XCHUNK);
        float4 v2 = *(const float4*)(X + i + 2*XCHUNK);
        float4 v3 = *(const float4*)(X + i + 3*XCHUNK);
        *(__half2*)(g_xh + i)                  = __floats2half2_rn(v0.x, v0.y);
        *(__half2*)(g_xh + i + 2)              = __floats2half2_rn(v0.z, v0.w);
        *(__half2*)(g_xh + i + XCHUNK)         = __floats2half2_rn(v1.x, v1.y);
        *(__half2*)(g_xh + i + XCHUNK + 2)     = __floats2half2_rn(v1.z, v1.w);
        *(__half2*)(g_xh + i + 2*XCHUNK)       = __floats2half2_rn(v2.x, v2.y);
        *(__half2*)(g_xh + i + 2*XCHUNK + 2)   = __floats2half2_rn(v2.z, v2.w);
        *(__half2*)(g_xh + i + 3*XCHUNK)       = __floats2half2_rn(v3.x, v3.y);
        *(__half2*)(g_xh + i + 3*XCHUNK + 2)   = __floats2half2_rn(v3.z, v3.w);
    } else if (blk < 7168) {
        int r = blk - 4096;                             // 0..3071
        const float* src = (r < 1024) ? Wq : (r < 2048) ? Wk : Wv;
        int lr = r & 1023;
        int c = tid * 4;
        float4 v = *(const float4*)(src + (size_t)lr * DD + c);
        *(__half2*)(g_wh + (size_t)r * DD + c)     = __floats2half2_rn(v.x, v.y);
        *(__half2*)(g_wh + (size_t)r * DD + c + 2) = __floats2half2_rn(v.z, v.w);
    } else if (blk < 8192) {
        __shared__ float srow[DD];
        const int j = blk - 7168;
#pragma unroll
        for (int i = 0; i < 4; ++i) srow[tid + 256*i] = Wo[(size_t)j*DD + tid + 256*i];
        __syncthreads();
#pragma unroll
        for (int i = 0; i < 4; ++i) {
            int f = tid + 256*i;                         // f = h*64 + t
            g_woph[(size_t)j*DD + f] = __float2half_rn(srow[((f & 63) << 4) | (f >> 6)]);
        }
    } else {
        int idx = (blk - 8192) * 256 + tid;              // 0..3071
        int t = idx >> 10;
        const float* src = (t == 0) ? bq : (t == 1) ? bk : bv;
        g_bqkv[idx] = src[idx & 1023];
    }
}

// =============================================================================
// FP16 tensor-core GEMM:  C = A @ B^T + bias   (frozen at R11)
// =============================================================================
#define STA  16384                 // A stage bytes (128 rows x 128B)
#define STS_ (2*STA)               // 32768
#define GSMEM (3 * STS_)           // 98304
#define NKT  16                    // 1024 / 64

__global__ void __launch_bounds__(128, 2) gemm_h(
    const __half* __restrict__ A, const __half* __restrict__ B,
    const float* __restrict__ bias,
    void* __restrict__ o0, void* __restrict__ o1, void* __restrict__ o2,
    int half_out)
{
    extern __shared__ char smem[];
    const uint32_t sb = smem_u32(smem);
    const int tid  = threadIdx.x;
    const int wid  = tid >> 5;
    const int lane = tid & 31;
    const int n0 = blockIdx.x * 128;
    const int m0 = blockIdx.y * 128;
    const int wm = (wid & 1) * 64;
    const int wn = (wid >> 1) * 64;

    const int row0 = tid >> 3, seg = tid & 7;
    const uint32_t sm_base = (uint32_t)(row0*128 + ((seg ^ (row0 & 7)) << 4));
    const char* Abase = (const char*)A + (size_t)m0 * 2048 + row0*2048 + seg*16;
    const char* Bbase = (const char*)B + (size_t)n0 * 2048 + row0*2048 + seg*16;

#define LOADC(c) do {                                                    \
        uint32_t ab_ = sb + ((c) % 3)*STS_ + sm_base;                    \
        uint32_t bb_ = ab_ + STA;                                        \
        const char* ga_ = Abase + (size_t)(c)*128;                       \
        const char* gb_ = Bbase + (size_t)(c)*128;                       \
        _Pragma("unroll") for (int i_ = 0; i_ < 8; ++i_) {               \
            cp16(ab_ + i_*2048, ga_ + i_*32768);                         \
            cp16(bb_ + i_*2048, gb_ + i_*32768);                         \
        }                                                                \
        asm volatile("cp.async.commit_group;" ::: "memory");             \
    } while (0)

    const int a_row = wm + (lane & 15);
    const int b_row = wn + (lane & 7) + ((lane >> 4) << 3);
    const int lo4   = (lane & 7) << 4;
    const int a_hi  = lane >> 4;
    const int b_hi  = (lane >> 3) & 1;

    float acc[4][8][4];
#pragma unroll
    for (int i = 0; i < 4; ++i)
#pragma unroll
        for (int j = 0; j < 8; ++j)
#pragma unroll
            for (int t = 0; t < 4; ++t) acc[i][j][t] = 0.f;

    LOADC(0);
    LOADC(1);

    for (int kt = 0; kt < NKT; ++kt) {
        if (kt + 1 < NKT) asm volatile("cp.async.wait_group 1;" ::: "memory");
        else              asm volatile("cp.async.wait_group 0;" ::: "memory");
        __syncthreads();

        const bool do_load = (kt + 2 < NKT);
        const uint32_t nab = sb + ((kt + 2) % 3)*STS_ + sm_base;
        const uint32_t nbb = nab + STA;
        const char* nga = Abase + (size_t)(kt + 2)*128;
        const char* ngb = Bbase + (size_t)(kt + 2)*128;

        const uint32_t sa = sb + (kt % 3) * STS_;
        const uint32_t aB = sa + a_row*128;
        const uint32_t bB = sa + STA + b_row*128;

#pragma unroll
        for (int s = 0; s < 4; ++s) {
            uint32_t af[4][4], bf[4][4];
            const uint32_t asg = (uint32_t)(((2*s + a_hi) << 4) ^ lo4);
            const uint32_t bsg = (uint32_t)(((2*s + b_hi) << 4) ^ lo4);
#pragma unroll
            for (int mt = 0; mt < 4; ++mt)
                ldsm4(af[mt], aB + mt*2048 + asg);
#pragma unroll
            for (int p = 0; p < 4; ++p)
                ldsm4(bf[p], bB + p*2048 + bsg);
            if (do_load) {
                cp16(nab + (2*s  )*2048, nga + (size_t)(2*s  )*32768);
                cp16(nab + (2*s+1)*2048, nga + (size_t)(2*s+1)*32768);
                cp16(nbb + (2*s  )*2048, ngb + (size_t)(2*s  )*32768);
                cp16(nbb + (2*s+1)*2048, ngb + (size_t)(2*s+1)*32768);
            }
#pragma unroll
            for (int mt = 0; mt < 4; ++mt)
#pragma unroll
                for (int nt = 0; nt < 8; ++nt)
                    mma16(acc[mt][nt], af[mt],
                          bf[nt >> 1][(nt & 1) * 2], bf[nt >> 1][(nt & 1) * 2 + 1]);
        }
        if (do_load)
            asm volatile("cp.async.commit_group;" ::: "memory");
    }

    if (half_out) {
        const int t = n0 >> 10;
        __half* outp = (t == 0) ? (__half*)o0 : (t == 1) ? (__half*)o1 : (__half*)o2;
#pragma unroll
        for (int mt = 0; mt < 4; ++mt) {
#pragma unroll
            for (int nt = 0; nt < 8; ++nt) {
                int row = m0 + wm + mt*16 + (lane >> 2);
                int gn  = n0 + wn + nt*8 + 2*(lane & 3);
                int col = gn & 1023;
                float b0 = bias[gn], b1 = bias[gn + 1];
                *(__half2*)&outp[(size_t)row * 1024 + col] =
                    __floats2half2_rn(acc[mt][nt][0] + b0, acc[mt][nt][1] + b1);
                *(__half2*)&outp[(size_t)(row + 8) * 1024 + col] =
                    __floats2half2_rn(acc[mt][nt][2] + b0, acc[mt][nt][3] + b1);
            }
        }
    } else {
        float* outp = (float*)o0;
#pragma unroll
        for (int mt = 0; mt < 4; ++mt) {
#pragma unroll
            for (int nt = 0; nt < 8; ++nt) {
                int row = m0 + wm + mt*16 + (lane >> 2);
                int gn  = n0 + wn + nt*8 + 2*(lane & 3);
                float b0 = bias[gn], b1 = bias[gn + 1];
                *(float2*)&outp[(size_t)row * 1024 + gn] =
                    make_float2(acc[mt][nt][0] + b0, acc[mt][nt][1] + b1);
                *(float2*)&outp[(size_t)(row + 8) * 1024 + gn] =
                    make_float2(acc[mt][nt][2] + b0, acc[mt][nt][3] + b1);
            }
        }
    }
}

// =============================================================================
// partial KV^T per (b,h): kvT[e][d] = sum_l v[l][e]*k[l][d]
// f16 mma16 with ldmatrix.trans; cp.async staging; f32 partial output.
// =============================================================================
#define KVCH (LPART/32)            // 16 chunks of 32 l-rows

__global__ void __launch_bounds__(256) kv_partial()
{
    const int bh = blockIdx.x, part = blockIdx.y;
    const int b = bh >> 4, h = bh & 15;

    __shared__ __half vs[3][32*64];
    __shared__ __half ks[3][32*64];
    const uint32_t vsb = smem_u32(vs);
    const uint32_t ksb = smem_u32(ks);

    const int tid  = threadIdx.x;
    const int lane = tid & 31;
    const int warp = tid >> 5;
    const int e0 = (warp >> 1) * 16;
    const int d0 = (warp & 1) * 32;

    const int srow = tid >> 3, sseg = tid & 7;
    const uint32_t sm_off = (uint32_t)(srow*128 + ((sseg ^ (srow & 7)) << 4));
    const size_t gbase = ((size_t)(part * LPART + srow) * BB + b) * DD
                       + (size_t)h * 64 + sseg * 8;

#define LOADKV(c) do {                                                   \
        size_t g_ = gbase + (size_t)(c) * 32 * BB * DD;                  \
        cp16(vsb + ((c) % 3) * 4096 + sm_off, g_vh + g_);                \
        cp16(ksb + ((c) % 3) * 4096 + sm_off, g_kh + g_);                \
        asm volatile("cp.async.commit_group;" ::: "memory");             \
    } while (0)

    const int a_lrow = (lane & 7) + ((lane >> 4) << 3);
    const int b_lrow = (lane & 7) + (((lane >> 3) & 1) << 3);
    const int a_cbyte = e0*2 + (((lane >> 3) & 1) << 4);
    const int b_cbyte0 = d0*2 + (((lane >> 4) & 1) << 4);

    float acc[4][4];
#pragma unroll
    for (int i = 0; i < 4; ++i)
#pragma unroll
        for (int t = 0; t < 4; ++t) acc[i][t] = 0.f;

    LOADKV(0);
    LOADKV(1);

    for (int it = 0; it < KVCH; ++it) {
        if (it + 1 < KVCH) asm volatile("cp.async.wait_group 1;" ::: "memory");
        else               asm volatile("cp.async.wait_group 0;" ::: "memory");
        __syncthreads();
        if (it + 2 < KVCH) LOADKV(it + 2);

        const uint32_t vB = vsb + (it % 3) * 4096;
        const uint32_t kB = ksb + (it % 3) * 4096;

#pragma unroll
        for (int s = 0; s < 2; ++s) {
            uint32_t af[4], bf[2][4];
            {
                int r = 16*s + a_lrow;
                ldsm4t(af, vB + r*128 + (uint32_t)(((a_cbyte >> 4) ^ (r & 7)) << 4));
            }
#pragma unroll
            for (int p = 0; p < 2; ++p) {
                int r = 16*s + b_lrow;
                int cb = b_cbyte0 + p*32;
                ldsm4t(bf[p], kB + r*128 + (uint32_t)(((cb >> 4) ^ (r & 7)) << 4));
            }
#pragma unroll
            for (int nt = 0; nt < 4; ++nt)
                mma16(acc[nt], af,
                      bf[nt >> 1][(nt & 1) * 2], bf[nt >> 1][(nt & 1) * 2 + 1]);
        }
        __syncthreads();
    }

    float* out = g_kvp + ((size_t)part * BH + bh) * 4096;
#pragma unroll
    for (int nt = 0; nt < 4; ++nt) {
        int e = e0 + (lane >> 2);
        int d = d0 + nt*8 + 2*(lane & 3);
        *(float2*)&out[(e    ) * 64 + d] = make_float2(acc[nt][0], acc[nt][1]);
        *(float2*)&out[(e + 8) * 64 + d] = make_float2(acc[nt][2], acc[nt][3]);
    }
}

// deterministic fixed-order reduce; grid (BH, 16); output f16
__global__ void kv_reduce() {
    const int bh = blockIdx.x;
    const int i  = blockIdx.y * 256 + threadIdx.x;      // 0..4095
    float s = 0.f;
#pragma unroll
    for (int p = 0; p < KV_PARTS; ++p)
        s += g_kvp[((size_t)p * BH + bh) * 4096 + i];
    g_kvTh[(size_t)bh * 4096 + i] = __float2half_rn(s);
}

// =============================================================================
// attn = (q @ kvT^T) * (0.125/scalar) per (b,h)   (frozen at R12)
// =============================================================================
__global__ void __launch_bounds__(128) attn_qkv(const float* __restrict__ scalar_ptr)
{
    const int lc = blockIdx.x;
    const int h  = blockIdx.y;
    const int b  = blockIdx.z;
    const int bh = b * 16 + h;
    const int l0 = lc * 64;

    __shared__ __half qs [64 * 64];
    __shared__ __half kvs[64 * 64];

    const uint32_t qsb = smem_u32(qs);
    const uint32_t kvb = smem_u32(kvs);

    const int tid  = threadIdx.x;
    const int lane = tid & 31;
    const int warp = tid >> 5;
    const int wm   = warp * 16;

#pragma unroll
    for (int i = 0; i < 4; ++i) {
        int s   = tid + 128 * i;
        int row = s >> 3, seg = s & 7;
        uint32_t dst = (uint32_t)(row*128 + ((seg ^ (row & 7)) << 4));
        const __half* qg = g_qh + ((size_t)(l0 + row) * BB + b) * DD
                                + (size_t)h * 64 + seg * 8;
        const __half* kg = g_kvTh + (size_t)bh * 4096 + (size_t)s * 8;
        cp16(qsb + dst, qg);
        cp16(kvb + dst, kg);
    }
    asm volatile("cp.async.commit_group;" ::: "memory");
    asm volatile("cp.async.wait_group 0;" ::: "memory");
    __syncthreads();

    const int a_row = wm + (lane & 15);
    const int b_row = (lane & 7) + ((lane >> 4) << 3);
    const int lo4   = (lane & 7) << 4;
    const int a_hi  = lane >> 4;
    const int b_hi  = (lane >> 3) & 1;
    const uint32_t aB = qsb + a_row*128;
    const uint32_t bB = kvb + b_row*128;

    float acc[8][4];
#pragma unroll
    for (int i = 0; i < 8; ++i)
#pragma unroll
        for (int t = 0; t < 4; ++t) acc[i][t] = 0.f;

#pragma unroll
    for (int s = 0; s < 4; ++s) {
        uint32_t af[4], bf[4][4];
        const uint32_t asg = (uint32_t)(((2*s + a_hi) << 4) ^ lo4);
        const uint32_t bsg = (uint32_t)(((2*s + b_hi) << 4) ^ lo4);
        ldsm4(af, aB + asg);
#pragma unroll
        for (int p = 0; p < 4; ++p)
            ldsm4(bf[p], bB + p*2048 + bsg);
#pragma unroll
        for (int nt = 0; nt < 8; ++nt)
            mma16(acc[nt], af,
                  bf[nt >> 1][(nt & 1) * 2], bf[nt >> 1][(nt & 1) * 2 + 1]);
    }

    const float scale = 0.125f / (*scalar_ptr);
#pragma unroll
    for (int nt = 0; nt < 8; ++nt) {
        int l = l0 + wm + (lane >> 2);
        int e = nt*8 + 2*(lane & 3);
        size_t o0 = ((size_t)l * BB + b) * DD + (size_t)h * 64 + e;
        size_t o1 = ((size_t)(l + 8) * BB + b) * DD + (size_t)h * 64 + e;
        *(__half2*)&g_ah[o0] = __floats2half2_rn(acc[nt][0]*scale, acc[nt][1]*scale);
        *(__half2*)&g_ah[o1] = __floats2half2_rn(acc[nt][2]*scale, acc[nt][3]*scale);
    }
}

// =============================================================================
// launch (R14 structure): serial prep_all; kv-proj; fork q-proj || kv chain;
// join; attn; out-proj.
// =============================================================================
extern "C" void kernel_launch(void* const* d_in, const int* in_sizes, int n_in,
                              void* d_out, int out_size) {
    const float* x      = (const float*)d_in[0];
    const float* Wq     = (const float*)d_in[2];
    const float* bq     = (const float*)d_in[3];
    const float* Wk     = (const float*)d_in[4];
    const float* bk     = (const float*)d_in[5];
    const float* Wv     = (const float*)d_in[6];
    const float* bv     = (const float*)d_in[7];
    const float* Wo     = (const float*)d_in[8];
    const float* bo     = (const float*)d_in[9];
    const float* scalar = (const float*)d_in[10];
    float* out = (float*)d_out;

    __half *xh, *wh, *woph, *ah, *qh, *kh, *vh;
    float *bqkv;
    cudaGetSymbolAddress((void**)&xh,   g_xh);
    cudaGetSymbolAddress((void**)&wh,   g_wh);
    cudaGetSymbolAddress((void**)&woph, g_woph);
    cudaGetSymbolAddress((void**)&ah,   g_ah);
    cudaGetSymbolAddress((void**)&qh,   g_qh);
    cudaGetSymbolAddress((void**)&kh,   g_kh);
    cudaGetSymbolAddress((void**)&vh,   g_vh);
    cudaGetSymbolAddress((void**)&bqkv, g_bqkv);

    static cudaStream_t s2 = nullptr;
    static cudaEvent_t ev1 = nullptr, ev2 = nullptr;
    if (!s2) {
        cudaStreamCreateWithFlags(&s2, cudaStreamNonBlocking);
        cudaEventCreateWithFlags(&ev1, cudaEventDisableTiming);
        cudaEventCreateWithFlags(&ev2, cudaEventDisableTiming);
        cudaFuncSetAttribute(gemm_h, cudaFuncAttributeMaxDynamicSharedMemorySize,
                             GSMEM);
    }

    // serial prep: x->f16 (4x ILP), pack W, permute Wo, pack biases
    prep_all<<<8204, 256>>>(x, Wq, Wk, Wv, bq, bk, bv, Wo);

    // k,v projection: N = 2048 (weights rows [1024, 3072) of g_wh)
    gemm_h<<<dim3(2*DD/128, ROWS/128), 128, GSMEM>>>(
        xh, wh + (size_t)DD*DD, bqkv + DD, kh, vh, vh, 1);

    // fork: kv chain on side stream, q projection on main stream (concurrent)
    cudaEventRecord(ev1, 0);
    cudaStreamWaitEvent(s2, ev1, 0);
    kv_partial<<<dim3(BH, KV_PARTS), 256, 0, s2>>>();
    kv_reduce<<<dim3(BH, 16), 256, 0, s2>>>();
    cudaEventRecord(ev2, s2);

    // q projection: N = 1024
    gemm_h<<<dim3(DD/128, ROWS/128), 128, GSMEM>>>(
        xh, wh, bqkv, qh, qh, qh, 1);

    // join
    cudaStreamWaitEvent(0, ev2, 0);

    attn_qkv<<<dim3(LL / 64, HH, BB), 128>>>(scalar);

    // output projection: N = 1024, fp32 output
    gemm_h<<<dim3(DD/128, ROWS/128), 128, GSMEM>>>(
        ah, woph, bo, out, out, out, 0);
}